// round 1
// baseline (speedup 1.0000x reference)
#include <cuda_runtime.h>
#include <cstdint>

#define N_ENT  100000
#define NQ     64
#define NT     100064          // N_ENT + NQ
#define D      128
#define HD     256             // H * D
#define E_EDGE 400000
#define E_TOT  500000          // E_EDGE + N_ENT self edges
#define R_REL  500
#define NEG    0.2f

// ---------------- static device scratch (no runtime allocation) ----------------
__device__ float g_xl[(size_t)NT * HD];     // x_l, [node][h*128+d]
__device__ float g_xr[(size_t)NT * HD];     // x_r
__device__ float g_erel[(R_REL + 1) * HD];  // rel_feat @ W_ea.T (row 500 = ones)
__device__ float g_hid[R_REL * HD];         // relu(relations @ W_ea.T)
__device__ float g_p[(size_t)E_TOT * 2];    // exp(logit) per edge per head
__device__ float g_den[(size_t)N_ENT * 2];  // softmax denominators per target

// ---------------- init: out-node region = bias, denom = 0 ----------------
__global__ void k_init(float* __restrict__ out, const float* __restrict__ bias) {
    int i = blockIdx.x * blockDim.x + threadIdx.x;
    if (i < N_ENT * D) out[i] = bias[i & (D - 1)];
    if (i < N_ENT * 2) g_den[i] = 0.f;
}

// ---------------- e_rel = rel_feat @ W_ea.T  (+ relu hidden for out_edge) ------
__global__ void k_rel(const float* __restrict__ relations, const float* __restrict__ Wea) {
    __shared__ float row[D];
    int r = blockIdx.x;          // 0..500
    int tid = threadIdx.x;       // 256
    if (tid < D) row[tid] = (r == R_REL) ? 1.f : relations[r * D + tid];
    __syncthreads();
    const float4* rv = (const float4*)row;
    const float4* wv = (const float4*)(Wea + (size_t)tid * D);
    float s = 0.f;
#pragma unroll
    for (int k = 0; k < D / 4; ++k) {
        float4 a = rv[k], b = wv[k];
        s += a.x * b.x + a.y * b.y + a.z * b.z + a.w * b.w;
    }
    g_erel[r * HD + tid] = s;
    if (r < R_REL) g_hid[r * HD + tid] = fmaxf(s, 0.f);
}

// ---------------- out_edge = hid @ W_le.T + b_le ----------------
__global__ void k_edgeout(const float* __restrict__ Wle, const float* __restrict__ ble,
                          float* __restrict__ out) {
    __shared__ float h[HD];
    int r = blockIdx.x;          // 0..499
    int tid = threadIdx.x;       // 128
    h[tid]       = g_hid[r * HD + tid];
    h[tid + 128] = g_hid[r * HD + tid + 128];
    __syncthreads();
    const float4* hv = (const float4*)h;
    const float4* wv = (const float4*)(Wle + (size_t)tid * HD);
    float s = ble[tid];
#pragma unroll
    for (int k = 0; k < HD / 4; ++k) {
        float4 a = hv[k], b = wv[k];
        s += a.x * b.x + a.y * b.y + a.z * b.z + a.w * b.w;
    }
    out[(size_t)N_ENT * D + r * D + tid] = s;
}

// ---------------- big GEMM: [x_l|x_r] = node @ [W_l;W_r].T + [b_l;b_r] --------
// BM=128, BN=128, K=128 (one shot). k-major smem, LDA=132 (float4-aligned, low conflict).
#define LDA 132
__global__ __launch_bounds__(256) void k_gemm(
    const float* __restrict__ ent, const float* __restrict__ qry,
    const float* __restrict__ Wl, const float* __restrict__ bl,
    const float* __restrict__ Wr, const float* __restrict__ br) {
    extern __shared__ float sm[];
    float* As = sm;                 // [k=128][m=128] (+pad)
    float* Bs = sm + 128 * LDA;     // [k=128][n=128]
    const int tid  = threadIdx.x;
    const int row0 = blockIdx.x * 128;
    const int col0 = blockIdx.y * 128;   // within 512 output cols

    const int kl = tid & 31;        // k lane
    const int ms = tid >> 5;        // m/n sub-row (8 per pass)
#pragma unroll
    for (int it = 0; it < 16; ++it) {
        int m = it * 8 + ms;
        int r = row0 + m;
        const float* p = nullptr;
        if (r < NT) p = (r < N_ENT) ? ent + (size_t)r * D : qry + (size_t)(r - N_ENT) * D;
#pragma unroll
        for (int ko = 0; ko < 128; ko += 32)
            As[(ko + kl) * LDA + m] = p ? p[ko + kl] : 0.f;
    }
#pragma unroll
    for (int it = 0; it < 16; ++it) {
        int n = it * 8 + ms;
        int c = col0 + n;
        const float* w = (c < HD) ? Wl + (size_t)c * D : Wr + (size_t)(c - HD) * D;
#pragma unroll
        for (int ko = 0; ko < 128; ko += 32)
            Bs[(ko + kl) * LDA + n] = w[ko + kl];
    }
    __syncthreads();

    const int tx = tid & 15, ty = tid >> 4;
    float acc[8][8];
#pragma unroll
    for (int i = 0; i < 8; ++i)
#pragma unroll
        for (int j = 0; j < 8; ++j) acc[i][j] = 0.f;

    const float* apt = As + ty * 8;
    const float* bpt = Bs + tx * 8;
#pragma unroll 4
    for (int k = 0; k < 128; ++k) {
        float4 a0 = *(const float4*)(apt + k * LDA);
        float4 a1 = *(const float4*)(apt + k * LDA + 4);
        float4 b0 = *(const float4*)(bpt + k * LDA);
        float4 b1 = *(const float4*)(bpt + k * LDA + 4);
        float av[8] = {a0.x, a0.y, a0.z, a0.w, a1.x, a1.y, a1.z, a1.w};
        float bv[8] = {b0.x, b0.y, b0.z, b0.w, b1.x, b1.y, b1.z, b1.w};
#pragma unroll
        for (int i = 0; i < 8; ++i)
#pragma unroll
            for (int j = 0; j < 8; ++j) acc[i][j] += av[i] * bv[j];
    }

#pragma unroll
    for (int i = 0; i < 8; ++i) {
        int r = row0 + ty * 8 + i;
        if (r >= NT) continue;
#pragma unroll
        for (int jo = 0; jo < 8; jo += 4) {
            int c = col0 + tx * 8 + jo;   // whole float4 stays on one side of 256
            float* dst;
            const float* bb;
            if (c < HD) { dst = g_xl + (size_t)r * HD + c;        bb = bl + c; }
            else        { dst = g_xr + (size_t)r * HD + (c - HD); bb = br + (c - HD); }
            float4 v;
            v.x = acc[i][jo + 0] + bb[0];
            v.y = acc[i][jo + 1] + bb[1];
            v.z = acc[i][jo + 2] + bb[2];
            v.w = acc[i][jo + 3] + bb[3];
            *(float4*)dst = v;
        }
    }
}

// ---------------- helpers for edge passes ----------------
__device__ __forceinline__ void edge_st(int gw, const int* __restrict__ ei,
                                        const int* __restrict__ batch,
                                        int& s, int& t) {
    if (gw < E_EDGE) { s = ei[gw]; t = ei[E_EDGE + gw]; }
    else             { int i = gw - E_EDGE; s = N_ENT + batch[i]; t = i; }
}
__device__ __forceinline__ float4 leaky4(float4 z) {
    z.x = z.x > 0.f ? z.x : NEG * z.x;
    z.y = z.y > 0.f ? z.y : NEG * z.y;
    z.z = z.z > 0.f ? z.z : NEG * z.z;
    z.w = z.w > 0.f ? z.w : NEG * z.w;
    return z;
}

// ---------------- edge pass 1: p = exp(logit), denom += p ----------------
__global__ void k_logits(const int* __restrict__ ei, const int* __restrict__ ridx,
                         const int* __restrict__ batch, const float* __restrict__ att) {
    int gw = (blockIdx.x * blockDim.x + threadIdx.x) >> 5;
    if (gw >= E_TOT) return;
    int lane = threadIdx.x & 31;
    int s, t;
    edge_st(gw, ei, batch, s, t);
    int rel = (gw < E_EDGE) ? ridx[gw] : R_REL;

    const float4* A  = (const float4*)g_xl + (size_t)s * 64;
    const float4* Xr = (const float4*)g_xr + (size_t)t * 64;
    const float4* Ee = (const float4*)g_erel + (size_t)rel * 64;
    const float4* At = (const float4*)att;

    float4 a = A[lane], b = Xr[lane], c = Ee[lane];
    float4 z = leaky4(make_float4(a.x + b.x + c.x, a.y + b.y + c.y,
                                  a.z + b.z + c.z, a.w + b.w + c.w));
    float4 ta = At[lane];
    float s0 = z.x * ta.x + z.y * ta.y + z.z * ta.z + z.w * ta.w;

    a = A[lane + 32]; b = Xr[lane + 32]; c = Ee[lane + 32];
    z = leaky4(make_float4(a.x + b.x + c.x, a.y + b.y + c.y,
                           a.z + b.z + c.z, a.w + b.w + c.w));
    ta = At[lane + 32];
    float s1 = z.x * ta.x + z.y * ta.y + z.z * ta.z + z.w * ta.w;

#pragma unroll
    for (int o = 16; o; o >>= 1) {
        s0 += __shfl_xor_sync(0xffffffffu, s0, o);
        s1 += __shfl_xor_sync(0xffffffffu, s1, o);
    }
    if (lane == 0) {
        float2 pv;
        pv.x = expf(s0);
        pv.y = expf(s1);
        ((float2*)g_p)[gw] = pv;
        atomicAdd((float2*)g_den + t, pv);   // sm_90+ vector RED
    }
}

// ---------------- edge pass 2: out[t] += 0.5 * (w0*xl_h0 + w1*xl_h1) ----------
__global__ void k_agg(const int* __restrict__ ei, const int* __restrict__ batch,
                      float* __restrict__ out) {
    int gw = (blockIdx.x * blockDim.x + threadIdx.x) >> 5;
    if (gw >= E_TOT) return;
    int lane = threadIdx.x & 31;
    int s, t;
    edge_st(gw, ei, batch, s, t);

    float2 p  = ((const float2*)g_p)[gw];
    float2 dn = ((const float2*)g_den)[t];
    float w0 = 0.5f * p.x / (dn.x + 1e-16f);
    float w1 = 0.5f * p.y / (dn.y + 1e-16f);

    const float4* A = (const float4*)g_xl + (size_t)s * 64;
    float4 a0 = A[lane], a1 = A[lane + 32];
    float4 v = make_float4(w0 * a0.x + w1 * a1.x, w0 * a0.y + w1 * a1.y,
                           w0 * a0.z + w1 * a1.z, w0 * a0.w + w1 * a1.w);
    atomicAdd((float4*)out + (size_t)t * 32 + lane, v);  // RED.128
}

// ---------------- launch ----------------
extern "C" void kernel_launch(void* const* d_in, const int* in_sizes, int n_in,
                              void* d_out, int out_size) {
    const float* queries        = (const float*)d_in[0];
    const float* entities       = (const float*)d_in[1];
    const int*   edge_index     = (const int*)d_in[2];
    const float* relations      = (const float*)d_in[3];
    const int*   relation_index = (const int*)d_in[4];
    const int*   batch          = (const int*)d_in[5];
    const float* W_l  = (const float*)d_in[6];
    const float* b_l  = (const float*)d_in[7];
    const float* W_r  = (const float*)d_in[8];
    const float* b_r  = (const float*)d_in[9];
    const float* W_ea = (const float*)d_in[10];
    const float* att  = (const float*)d_in[11];
    const float* bias = (const float*)d_in[12];
    const float* W_le = (const float*)d_in[13];
    const float* b_le = (const float*)d_in[14];
    float* out = (float*)d_out;

    k_init<<<(N_ENT * D + 255) / 256, 256>>>(out, bias);
    k_rel<<<R_REL + 1, 256>>>(relations, W_ea);
    k_edgeout<<<R_REL, 128>>>(W_le, b_le, out);

    const int smem = 2 * 128 * LDA * 4;   // 135168 B
    cudaFuncSetAttribute(k_gemm, cudaFuncAttributeMaxDynamicSharedMemorySize, smem);
    k_gemm<<<dim3((NT + 127) / 128, 4), 256, smem>>>(entities, queries, W_l, b_l, W_r, b_r);

    int edge_blocks = (E_TOT * 32 + 255) / 256;
    k_logits<<<edge_blocks, 256>>>(edge_index, relation_index, batch, att);
    k_agg<<<edge_blocks, 256>>>(edge_index, batch, out);
}

// round 3
// speedup vs baseline: 1.3513x; 1.3513x over previous
#include <cuda_runtime.h>
#include <cuda_bf16.h>
#include <cstdint>

#define N_ENT  100000
#define NQ     64
#define NT     100064
#define D      128
#define HD     256
#define E_EDGE 400000
#define E_TOT  500000
#define R_REL  500
#define NEG    0.2f

// ---------------- static device scratch ----------------
__device__ float g_xl[(size_t)NT * HD];
__device__ float g_xr[(size_t)NT * HD];
__device__ float g_erel[(R_REL + 1) * HD];
__device__ float g_hid[R_REL * HD];
__device__ float g_p[(size_t)E_TOT * 2];
__device__ float g_den[(size_t)N_ENT * 2];
__device__ __nv_bfloat16 g_wh[512 * 128];   // [outcol n][k] bf16 hi
__device__ __nv_bfloat16 g_wl[512 * 128];   // bf16 lo residual

// ---------------- helpers ----------------
__device__ __forceinline__ uint32_t smem_u32(const void* p) {
    uint32_t a;
    asm("{ .reg .u64 t; cvta.to.shared.u64 t, %1; cvt.u32.u64 %0, t; }" : "=r"(a) : "l"(p));
    return a;
}
__device__ __forceinline__ void ldsm_x4(uint32_t* r, uint32_t addr) {
    asm volatile("ldmatrix.sync.aligned.m8n8.x4.shared.b16 {%0,%1,%2,%3}, [%4];"
                 : "=r"(r[0]), "=r"(r[1]), "=r"(r[2]), "=r"(r[3]) : "r"(addr));
}
__device__ __forceinline__ void mma_bf16(float* d, const uint32_t* a, const uint32_t* b) {
    asm volatile("mma.sync.aligned.m16n8k16.row.col.f32.bf16.bf16.f32 "
                 "{%0,%1,%2,%3}, {%4,%5,%6,%7}, {%8,%9}, {%0,%1,%2,%3};"
                 : "+f"(d[0]), "+f"(d[1]), "+f"(d[2]), "+f"(d[3])
                 : "r"(a[0]), "r"(a[1]), "r"(a[2]), "r"(a[3]), "r"(b[0]), "r"(b[1]));
}

// smem tile geometry: 128 rows x 128 bf16 cols, pitch 272 B (conflict-free ldmatrix)
#define ROWB 272
#define SM_AHI 0
#define SM_ALO 34816
#define SM_BHI 69632
#define SM_BLO 104448
#define SM_TOTAL 139264

// ---------------- split W into bf16 hi/lo ----------------
__global__ void k_wsplit(const float* __restrict__ Wl, const float* __restrict__ Wr) {
    int i = blockIdx.x * 256 + threadIdx.x;
    if (i >= 512 * 128) return;
    int n = i >> 7, k = i & 127;
    float v = (n < 256) ? Wl[n * 128 + k] : Wr[(n - 256) * 128 + k];
    __nv_bfloat16 h = __float2bfloat16(v);
    g_wh[i] = h;
    g_wl[i] = __float2bfloat16(v - __bfloat162float(h));
}

// ---------------- HMMA GEMM: [x_l|x_r] = node @ [W_l;W_r].T + bias ----------------
__global__ __launch_bounds__(256) void k_gemm_mma(
    const float* __restrict__ ent, const float* __restrict__ qry,
    const float* __restrict__ bl, const float* __restrict__ br) {
    extern __shared__ char smem[];
    const uint32_t sb = smem_u32(smem);
    const int tid = threadIdx.x;
    const int wid = tid >> 5, lane = tid & 31;
    const int row0 = blockIdx.x * 128;

    // ---- convert A tile fp32 -> bf16 hi/lo into smem ----
#pragma unroll
    for (int i = 0; i < 16; ++i) {
        int idx = i * 256 + tid;          // 0..4095
        int r = idx >> 5, c4 = (idx & 31) * 4;
        int gr = row0 + r;
        float4 v = make_float4(0.f, 0.f, 0.f, 0.f);
        if (gr < N_ENT)   v = *(const float4*)(ent + (size_t)gr * D + c4);
        else if (gr < NT) v = *(const float4*)(qry + (size_t)(gr - N_ENT) * D + c4);
        float f[4] = {v.x, v.y, v.z, v.w};
        uint32_t h01 = 0, h23 = 0, l01 = 0, l23 = 0;
#pragma unroll
        for (int j = 0; j < 4; ++j) {
            __nv_bfloat16 hb = __float2bfloat16(f[j]);
            __nv_bfloat16 lb = __float2bfloat16(f[j] - __bfloat162float(hb));
            uint32_t hu = *(unsigned short*)&hb, lu = *(unsigned short*)&lb;
            if (j < 2) { h01 |= hu << (16 * j);       l01 |= lu << (16 * j); }
            else       { h23 |= hu << (16 * (j - 2)); l23 |= lu << (16 * (j - 2)); }
        }
        uint32_t off = (uint32_t)(r * ROWB + c4 * 2);
        *(uint2*)(smem + SM_AHI + off) = make_uint2(h01, h23);
        *(uint2*)(smem + SM_ALO + off) = make_uint2(l01, l23);
    }
    __syncthreads();

    const int wm = wid & 3;     // 4 m-groups of 32 rows
    const int wn = wid >> 2;    // 2 n-groups of 64 cols

    for (int t = 0; t < 4; ++t) {
        // ---- load B tile (rows t*128.. of W, bf16 hi/lo) ----
        const __nv_bfloat16* wh = g_wh + (size_t)t * 128 * 128;
        const __nv_bfloat16* wl = g_wl + (size_t)t * 128 * 128;
#pragma unroll
        for (int i = 0; i < 8; ++i) {
            int idx = i * 256 + tid;      // 0..2047
            int r = idx >> 4, c8 = (idx & 15) * 8;
            uint32_t off = (uint32_t)(r * ROWB + c8 * 2);
            *(uint4*)(smem + SM_BHI + off) = *(const uint4*)(wh + r * 128 + c8);
            *(uint4*)(smem + SM_BLO + off) = *(const uint4*)(wl + r * 128 + c8);
        }
        __syncthreads();

        float acc[2][8][4];
#pragma unroll
        for (int a = 0; a < 2; ++a)
#pragma unroll
            for (int b = 0; b < 8; ++b)
#pragma unroll
                for (int c = 0; c < 4; ++c) acc[a][b][c] = 0.f;

        // a ldmatrix addressing: lanes 0-15 rows m0-15 (k lo), 16-31 same rows (k hi)
        const int am = wm * 32 + (lane & 15);
        const int ak = (lane >> 4) * 8;
        // b ldmatrix addressing: bit4 -> n-subtile(+8), bit3 -> k-half(+8)
        const int bn = wn * 64 + ((lane >> 4) & 1) * 8 + (lane & 7);
        const int bk = ((lane >> 3) & 1) * 8;

#pragma unroll
        for (int ks = 0; ks < 8; ++ks) {
            uint32_t ah[2][4], alo[2][4];
#pragma unroll
            for (int mi = 0; mi < 2; ++mi) {
                uint32_t addr = sb + SM_AHI + (uint32_t)((am + mi * 16) * ROWB + (ks * 16 + ak) * 2);
                ldsm_x4(ah[mi], addr);
                ldsm_x4(alo[mi], addr + (SM_ALO - SM_AHI));
            }
#pragma unroll
            for (int ntp = 0; ntp < 4; ++ntp) {
                uint32_t baddr = sb + SM_BHI +
                    (uint32_t)((bn + ntp * 16) * ROWB + (ks * 16 + bk) * 2);
                uint32_t bh[4], blo[4];
                ldsm_x4(bh, baddr);
                ldsm_x4(blo, baddr + (SM_BLO - SM_BHI));
#pragma unroll
                for (int mi = 0; mi < 2; ++mi) {
                    mma_bf16(acc[mi][2 * ntp],     ah[mi],  bh);
                    mma_bf16(acc[mi][2 * ntp],     ah[mi],  blo);
                    mma_bf16(acc[mi][2 * ntp],     alo[mi], bh);
                    mma_bf16(acc[mi][2 * ntp + 1], ah[mi],  bh + 2);
                    mma_bf16(acc[mi][2 * ntp + 1], ah[mi],  blo + 2);
                    mma_bf16(acc[mi][2 * ntp + 1], alo[mi], bh + 2);
                }
            }
        }
        __syncthreads();   // all warps done reading B smem before next iter's load

        // ---- epilogue: regs -> g_xl / g_xr with bias ----
        const int gid = lane >> 2, tig = lane & 3;
#pragma unroll
        for (int mi = 0; mi < 2; ++mi) {
            int r1 = row0 + wm * 32 + mi * 16 + gid;
            int r2 = r1 + 8;
#pragma unroll
            for (int ni = 0; ni < 8; ++ni) {
                int cg = t * 128 + wn * 64 + ni * 8 + tig * 2;  // 0..511
                float* base;
                const float* bb;
                int c;
                if (cg < HD) { base = g_xl; c = cg;      bb = bl; }
                else         { base = g_xr; c = cg - HD; bb = br; }
                float2 bv = *(const float2*)(bb + c);
                if (r1 < NT) {
                    float2 o = make_float2(acc[mi][ni][0] + bv.x, acc[mi][ni][1] + bv.y);
                    *(float2*)(base + (size_t)r1 * HD + c) = o;
                }
                if (r2 < NT) {
                    float2 o = make_float2(acc[mi][ni][2] + bv.x, acc[mi][ni][3] + bv.y);
                    *(float2*)(base + (size_t)r2 * HD + c) = o;
                }
            }
        }
    }
}

// ---------------- init ----------------
__global__ void k_init(float* __restrict__ out, const float* __restrict__ bias) {
    int i = blockIdx.x * blockDim.x + threadIdx.x;
    if (i < N_ENT * D) out[i] = bias[i & (D - 1)];
    if (i < N_ENT * 2) g_den[i] = 0.f;
}

// ---------------- e_rel = rel_feat @ W_ea.T ----------------
__global__ void k_rel(const float* __restrict__ relations, const float* __restrict__ Wea) {
    __shared__ float row[D];
    int r = blockIdx.x;
    int tid = threadIdx.x;
    if (tid < D) row[tid] = (r == R_REL) ? 1.f : relations[r * D + tid];
    __syncthreads();
    const float4* rv = (const float4*)row;
    const float4* wv = (const float4*)(Wea + (size_t)tid * D);
    float s = 0.f;
#pragma unroll
    for (int k = 0; k < D / 4; ++k) {
        float4 a = rv[k], b = wv[k];
        s += a.x * b.x + a.y * b.y + a.z * b.z + a.w * b.w;
    }
    g_erel[r * HD + tid] = s;
    if (r < R_REL) g_hid[r * HD + tid] = fmaxf(s, 0.f);
}

// ---------------- out_edge ----------------
__global__ void k_edgeout(const float* __restrict__ Wle, const float* __restrict__ ble,
                          float* __restrict__ out) {
    __shared__ float h[HD];
    int r = blockIdx.x;
    int tid = threadIdx.x;
    h[tid]       = g_hid[r * HD + tid];
    h[tid + 128] = g_hid[r * HD + tid + 128];
    __syncthreads();
    const float4* hv = (const float4*)h;
    const float4* wv = (const float4*)(Wle + (size_t)tid * HD);
    float s = ble[tid];
#pragma unroll
    for (int k = 0; k < HD / 4; ++k) {
        float4 a = hv[k], b = wv[k];
        s += a.x * b.x + a.y * b.y + a.z * b.z + a.w * b.w;
    }
    out[(size_t)N_ENT * D + r * D + tid] = s;
}

// ---------------- edge helpers ----------------
__device__ __forceinline__ void edge_st(int gw, const int* __restrict__ ei,
                                        const int* __restrict__ batch, int& s, int& t) {
    if (gw < E_EDGE) { s = ei[gw]; t = ei[E_EDGE + gw]; }
    else             { int i = gw - E_EDGE; s = N_ENT + batch[i]; t = i; }
}
__device__ __forceinline__ float4 leaky4(float4 z) {
    z.x = z.x > 0.f ? z.x : NEG * z.x;
    z.y = z.y > 0.f ? z.y : NEG * z.y;
    z.z = z.z > 0.f ? z.z : NEG * z.z;
    z.w = z.w > 0.f ? z.w : NEG * z.w;
    return z;
}

// ---------------- edge pass 1: logits ----------------
__global__ void k_logits(const int* __restrict__ ei, const int* __restrict__ ridx,
                         const int* __restrict__ batch, const float* __restrict__ att) {
    int gw = (blockIdx.x * blockDim.x + threadIdx.x) >> 5;
    if (gw >= E_TOT) return;
    int lane = threadIdx.x & 31;
    int s, t;
    edge_st(gw, ei, batch, s, t);
    int rel = (gw < E_EDGE) ? ridx[gw] : R_REL;

    const float4* A  = (const float4*)g_xl + (size_t)s * 64;
    const float4* Xr = (const float4*)g_xr + (size_t)t * 64;
    const float4* Ee = (const float4*)g_erel + (size_t)rel * 64;
    const float4* At = (const float4*)att;

    float4 a = A[lane], b = Xr[lane], c = Ee[lane];
    float4 z = leaky4(make_float4(a.x + b.x + c.x, a.y + b.y + c.y,
                                  a.z + b.z + c.z, a.w + b.w + c.w));
    float4 ta = At[lane];
    float s0 = z.x * ta.x + z.y * ta.y + z.z * ta.z + z.w * ta.w;

    a = A[lane + 32]; b = Xr[lane + 32]; c = Ee[lane + 32];
    z = leaky4(make_float4(a.x + b.x + c.x, a.y + b.y + c.y,
                           a.z + b.z + c.z, a.w + b.w + c.w));
    ta = At[lane + 32];
    float s1 = z.x * ta.x + z.y * ta.y + z.z * ta.z + z.w * ta.w;

#pragma unroll
    for (int o = 16; o; o >>= 1) {
        s0 += __shfl_xor_sync(0xffffffffu, s0, o);
        s1 += __shfl_xor_sync(0xffffffffu, s1, o);
    }
    if (lane == 0) {
        float2 pv;
        pv.x = expf(s0);
        pv.y = expf(s1);
        ((float2*)g_p)[gw] = pv;
        atomicAdd((float2*)g_den + t, pv);
    }
}

// ---------------- edge pass 2: aggregation ----------------
__global__ void k_agg(const int* __restrict__ ei, const int* __restrict__ batch,
                      float* __restrict__ out) {
    int gw = (blockIdx.x * blockDim.x + threadIdx.x) >> 5;
    if (gw >= E_TOT) return;
    int lane = threadIdx.x & 31;
    int s, t;
    edge_st(gw, ei, batch, s, t);

    float2 p  = ((const float2*)g_p)[gw];
    float2 dn = ((const float2*)g_den)[t];
    float w0 = 0.5f * p.x / (dn.x + 1e-16f);
    float w1 = 0.5f * p.y / (dn.y + 1e-16f);

    const float4* A = (const float4*)g_xl + (size_t)s * 64;
    float4 a0 = A[lane], a1 = A[lane + 32];
    float4 v = make_float4(w0 * a0.x + w1 * a1.x, w0 * a0.y + w1 * a1.y,
                           w0 * a0.z + w1 * a1.z, w0 * a0.w + w1 * a1.w);
    atomicAdd((float4*)out + (size_t)t * 32 + lane, v);
}

// ---------------- launch ----------------
extern "C" void kernel_launch(void* const* d_in, const int* in_sizes, int n_in,
                              void* d_out, int out_size) {
    const float* queries        = (const float*)d_in[0];
    const float* entities       = (const float*)d_in[1];
    const int*   edge_index     = (const int*)d_in[2];
    const float* relations      = (const float*)d_in[3];
    const int*   relation_index = (const int*)d_in[4];
    const int*   batch          = (const int*)d_in[5];
    const float* W_l  = (const float*)d_in[6];
    const float* b_l  = (const float*)d_in[7];
    const float* W_r  = (const float*)d_in[8];
    const float* b_r  = (const float*)d_in[9];
    const float* W_ea = (const float*)d_in[10];
    const float* att  = (const float*)d_in[11];
    const float* bias = (const float*)d_in[12];
    const float* W_le = (const float*)d_in[13];
    const float* b_le = (const float*)d_in[14];
    float* out = (float*)d_out;

    k_init<<<(N_ENT * D + 255) / 256, 256>>>(out, bias);
    k_wsplit<<<(512 * 128 + 255) / 256, 256>>>(W_l, W_r);
    k_rel<<<R_REL + 1, 256>>>(relations, W_ea);
    k_edgeout<<<R_REL, 128>>>(W_le, b_le, out);

    cudaFuncSetAttribute(k_gemm_mma, cudaFuncAttributeMaxDynamicSharedMemorySize, SM_TOTAL);
    k_gemm_mma<<<(NT + 127) / 128, 256, SM_TOTAL>>>(entities, queries, b_l, b_r);

    int edge_blocks = (E_TOT * 32 + 255) / 256;
    k_logits<<<edge_blocks, 256>>>(edge_index, relation_index, batch, att);
    k_agg<<<edge_blocks, 256>>>(edge_index, batch, out);
}